// round 11
// baseline (speedup 1.0000x reference)
#include <cuda_runtime.h>
#include <cuda_bf16.h>

// LSEP loss, factorized:
//   S_b = (sum_{neg} e^{x}) * (sum_{pos} e^{-x});  loss = mean_b log1p(S_b)
// N = 512 rows, C = 512 cols.
//
// Single kernel node. 128 CTAs x 512 threads (4 rows per CTA); exactly one
// float4 + one int4 load per thread. Cross-CTA combine = ONE 64-bit integer
// atomicAdd per CTA into g_pack:
//   bits [52..62) : arrival count (each CTA adds 1<<52; target 127)
//   bits [0..52)  : fixed-point sum of log1p(S_row), scale 2^26
// Deterministic (integer adds). Last CTA publishes out[0]; reset is a plain
// store. Replay-idempotent, no memset node, no fences.
//
// R11: half-warp combined reduction (6 shuffles instead of 10: lanes 0-15
// carry the pos-sum, lanes 16-31 the neg-sum after one exchange at offset 16),
// SEL-routed accumulate (no I2F / dual-FMA on the chain).

#define NROWS 512
#define NCOLS 512
#define ROWS_PER_CTA 4
#define NBLOCKS (NROWS / ROWS_PER_CTA)   // 128
#define NTHREADS (128 * ROWS_PER_CTA)    // 512

#define CNT_ONE  (1ULL << 52)
#define VAL_MASK (CNT_ONE - 1ULL)
#define FP_SCALE 67108864.0f   // 2^26

__device__ unsigned long long g_pack;   // zero-initialized; reset each run

__global__ void __launch_bounds__(NTHREADS) lsep_kernel(
    const int* __restrict__ y_true,
    const float* __restrict__ y_pred,
    float* __restrict__ out)
{
    const int t       = threadIdx.x;
    const int row_loc = t >> 7;                 // 0..3 within CTA
    const int idx     = t & 127;                // float4 index within row
    const int row     = blockIdx.x * ROWS_PER_CTA + row_loc;

    const float4* __restrict__ pv = reinterpret_cast<const float4*>(y_pred + row * NCOLS);
    const int4*   __restrict__ tv = reinterpret_cast<const int4*>(y_true + row * NCOLS);

    float4 v = pv[idx];
    int4   l = tv[idx];

    float pos = 0.f, neg = 0.f;

    // Branchless sign flip + SEL-routed accumulate (no I2F, no FMA pair).
#define ACC(LBL, VAL) do {                                              \
        float x = __int_as_float(__float_as_int(VAL) ^ ((LBL) << 31));  \
        float e = __expf(x);                                            \
        pos += (LBL) ? e : 0.0f;                                        \
        neg += (LBL) ? 0.0f : e;                                        \
    } while (0)

    ACC(l.x, v.x);
    ACC(l.y, v.y);
    ACC(l.z, v.z);
    ACC(l.w, v.w);
#undef ACC

    const int wid  = t >> 5;    // warps 4r..4r+3 belong to row r
    const int lane = t & 31;

    // Half-warp combined reduction: one exchange at offset 16, then lanes
    // 0-15 reduce the pos-sum while lanes 16-31 reduce the neg-sum (xor
    // offsets < 16 keep the halves separate). 6 shuffles total.
    {
        float po = __shfl_xor_sync(0xFFFFFFFFu, pos, 16);
        float ne = __shfl_xor_sync(0xFFFFFFFFu, neg, 16);
        float comb = (lane < 16) ? (pos + po) : (neg + ne);
        #pragma unroll
        for (int off = 8; off > 0; off >>= 1)
            comb += __shfl_xor_sync(0xFFFFFFFFu, comb, off);
        pos = comb;            // valid on lanes 0-15
        neg = comb;            // valid on lanes 16-31
    }

    __shared__ float s_pos[16];
    __shared__ float s_neg[16];
    if (lane == 0)  s_pos[wid] = pos;
    if (lane == 16) s_neg[wid] = neg;
    __syncthreads();

    if (wid == 0) {
        // lanes 0..3 each finalize one row; other lanes contribute 0
        float contrib = 0.f;
        if (lane < ROWS_PER_CTA) {
            const int r4 = lane * 4;
            float p = s_pos[r4] + s_pos[r4 + 1] + s_pos[r4 + 2] + s_pos[r4 + 3];
            float n = s_neg[r4] + s_neg[r4 + 1] + s_neg[r4 + 2] + s_neg[r4 + 3];
            contrib = __logf(1.0f + p * n);
        }
        contrib += __shfl_xor_sync(0xFFFFFFFFu, contrib, 2);
        contrib += __shfl_xor_sync(0xFFFFFFFFu, contrib, 1);

        if (lane == 0) {
            // fixed-point encode in fp32 (quantization ~5e-7 absolute per row)
            unsigned long long fx = (unsigned long long)(contrib * FP_SCALE);
            unsigned long long prev = atomicAdd(&g_pack, CNT_ONE | fx);

            if ((prev >> 52) == (unsigned long long)(NBLOCKS - 1)) {
                unsigned long long total_fx = (prev & VAL_MASK) + fx;
                float total = (float)total_fx * (1.0f / FP_SCALE);
                out[0] = total * (1.0f / (float)NROWS);
                // After count saturation no other CTA touches g_pack:
                // plain store reset is race-free.
                *(volatile unsigned long long*)&g_pack = 0ULL;
            }
        }
    }
}

extern "C" void kernel_launch(void* const* d_in, const int* in_sizes, int n_in,
                              void* d_out, int out_size)
{
    const int*   y_true = (const int*)d_in[0];
    const float* y_pred = (const float*)d_in[1];
    float* out = (float*)d_out;

    lsep_kernel<<<NBLOCKS, NTHREADS>>>(y_true, y_pred, out);
}

// round 12
// speedup vs baseline: 1.0248x; 1.0248x over previous
#include <cuda_runtime.h>
#include <cuda_bf16.h>

// LSEP loss, factorized:
//   S_b = (sum_{neg} e^{x}) * (sum_{pos} e^{-x});  loss = mean_b log1p(S_b)
// N = 512 rows, C = 512 cols.
//
// Single kernel node. 256 CTAs x 256 threads (2 rows per CTA); exactly one
// float4 + one int4 load per thread (proven fastest per-thread shape).
// Cross-CTA combine = ONE 64-bit integer atomicAdd per CTA into g_pack:
//   bits [52..62) : arrival count (each CTA adds 1<<52; target 255)
//   bits [0..52)  : fixed-point sum of log1p(S_row), scale 2^26
// Deterministic (integer adds). Last CTA publishes out[0]; reset is a plain
// store (nobody touches g_pack after count saturation). Replay-idempotent,
// no memset node, no fences.
//
// R12 = R10's proven body/reduction (dual pipelined shuffle chains) with
// 8 warps/CTA instead of 16 to shrink the barrier straggler wait.

#define NROWS 512
#define NCOLS 512
#define ROWS_PER_CTA 2
#define NBLOCKS (NROWS / ROWS_PER_CTA)   // 256
#define NTHREADS (128 * ROWS_PER_CTA)    // 256

#define CNT_ONE  (1ULL << 52)
#define VAL_MASK (CNT_ONE - 1ULL)
#define FP_SCALE 67108864.0f   // 2^26

__device__ unsigned long long g_pack;   // zero-initialized; reset each run

__global__ void __launch_bounds__(NTHREADS) lsep_kernel(
    const int* __restrict__ y_true,
    const float* __restrict__ y_pred,
    float* __restrict__ out)
{
    const int t       = threadIdx.x;
    const int row_loc = t >> 7;                 // 0..1 within CTA
    const int idx     = t & 127;                // float4 index within row
    const int row     = blockIdx.x * ROWS_PER_CTA + row_loc;

    const float4* __restrict__ pv = reinterpret_cast<const float4*>(y_pred + row * NCOLS);
    const int4*   __restrict__ tv = reinterpret_cast<const int4*>(y_true + row * NCOLS);

    float4 v = pv[idx];
    int4   l = tv[idx];

    float pos = 0.f, neg = 0.f;

    // Branchless sign flip; route e into pos/neg via FMA pair (R10 form).
#define ACC(LBL, VAL) do {                                              \
        float x = __int_as_float(__float_as_int(VAL) ^ ((LBL) << 31));  \
        float e = __expf(x);                                            \
        float fl = (float)(LBL);                                        \
        pos = fmaf(fl, e, pos);                                         \
        neg = fmaf(1.0f - fl, e, neg);                                  \
    } while (0)

    ACC(l.x, v.x);
    ACC(l.y, v.y);
    ACC(l.z, v.z);
    ACC(l.w, v.w);
#undef ACC

    // warp reduction: two independent shuffle chains (pipelined)
    #pragma unroll
    for (int off = 16; off > 0; off >>= 1) {
        pos += __shfl_xor_sync(0xFFFFFFFFu, pos, off);
        neg += __shfl_xor_sync(0xFFFFFFFFu, neg, off);
    }

    __shared__ float s_pos[8];
    __shared__ float s_neg[8];
    const int wid  = t >> 5;    // warps 4r..4r+3 belong to row r (r = wid>>2)
    const int lane = t & 31;
    if (lane == 0) { s_pos[wid] = pos; s_neg[wid] = neg; }
    __syncthreads();

    if (wid == 0) {
        // lanes 0..1 each finalize one row; other lanes contribute 0
        float contrib = 0.f;
        if (lane < ROWS_PER_CTA) {
            const int r4 = lane * 4;
            float p = s_pos[r4] + s_pos[r4 + 1] + s_pos[r4 + 2] + s_pos[r4 + 3];
            float n = s_neg[r4] + s_neg[r4 + 1] + s_neg[r4 + 2] + s_neg[r4 + 3];
            contrib = __logf(1.0f + p * n);
        }
        contrib += __shfl_xor_sync(0xFFFFFFFFu, contrib, 1);

        if (lane == 0) {
            // fixed-point encode in fp32 (quantization ~5e-7 absolute per row)
            unsigned long long fx = (unsigned long long)(contrib * FP_SCALE);
            unsigned long long prev = atomicAdd(&g_pack, CNT_ONE | fx);

            if ((prev >> 52) == (unsigned long long)(NBLOCKS - 1)) {
                unsigned long long total_fx = (prev & VAL_MASK) + fx;
                float total = (float)total_fx * (1.0f / FP_SCALE);
                out[0] = total * (1.0f / (float)NROWS);
                // After count saturation no other CTA touches g_pack:
                // plain store reset is race-free.
                *(volatile unsigned long long*)&g_pack = 0ULL;
            }
        }
    }
}

extern "C" void kernel_launch(void* const* d_in, const int* in_sizes, int n_in,
                              void* d_out, int out_size)
{
    const int*   y_true = (const int*)d_in[0];
    const float* y_pred = (const float*)d_in[1];
    float* out = (float*)d_out;

    lsep_kernel<<<NBLOCKS, NTHREADS>>>(y_true, y_pred, out);
}